// round 7
// baseline (speedup 1.0000x reference)
#include <cuda_runtime.h>
#include <math.h>

#define NB 8
#define NH 32
#define DK 128
#define DM 4096
#define MAXLEN 4096
#define CACHE_LEN 4095
#define SEQ_L 4096
#define NPAIR (NB*NH)                 // 256
#define SPLIT 8
#define KEYS_PER_BLOCK (SEQ_L/SPLIT)  // 512
#define AWARPS 8
#define KEYS_PER_WARP (KEYS_PER_BLOCK/AWARPS) // 64
#define PART_STRIDE 132               // m, s, pad, pad, vec[128]  (528B, 16B-aligned)
#define GR 2                          // rows per warp in GEMV
#define ROWS_PER_BLOCK 4              // 2 row-groups x 2 rows, 4-way column split

// Scratch (no allocations allowed in kernel_launch)
__device__ float g_qkv[3 * NB * DM];                    // q (pre-scaled) | k_new | v_new
__device__ float g_part[NPAIR * SPLIT * PART_STRIDE];   // split-K partials
__device__ float g_attn[NB * DM];                       // combined attention output

__device__ __forceinline__ float wredsum(float v) {
    v += __shfl_xor_sync(0xffffffffu, v, 16);
    v += __shfl_xor_sync(0xffffffffu, v, 8);
    v += __shfl_xor_sync(0xffffffffu, v, 4);
    v += __shfl_xor_sync(0xffffffffu, v, 2);
    v += __shfl_xor_sync(0xffffffffu, v, 1);
    return v;
}

// Packed f32x2 FMA: d = a*b + d elementwise on two packed floats.
__device__ __forceinline__ void fma2(unsigned long long& d,
                                     unsigned long long a,
                                     unsigned long long b) {
    asm("fma.rn.f32x2 %0, %1, %2, %0;" : "+l"(d) : "l"(a), "l"(b));
}
__device__ __forceinline__ float2 upk(unsigned long long v) {
    float2 r;
    asm("mov.b64 {%0, %1}, %2;" : "=f"(r.x), "=f"(r.y) : "l"(v));
    return r;
}

// ---------------------------------------------------------------------------
// GEMV block routine: block (256 thr, 8 warps) computes 4 output rows for all
// 8 batches. Warp w: row-group (w&1) [2 rows], column quarter (w>>1)
// [256 float4s -> 8 lane-strided iterations]. Quarters combined via smem.
// Register budget engineered for 4 CTAs/SM (<=64 regs):
//   acc 2x8 packed = 32, W 2x ulonglong2 = 8, one xv at a time = 4, ptrs ~12.
// W streamed (__ldcs) and issued first each iteration.
// ---------------------------------------------------------------------------
__device__ __forceinline__ void gemv_block(
    const float* __restrict__ W, const float* __restrict__ bias,
    const float* __restrict__ x, float* __restrict__ y,
    float scale, int row_base)
{
    int wid  = threadIdx.x >> 5;
    int lane = threadIdx.x & 31;
    int rg   = wid & 1;          // row group 0..1 (2 rows each)
    int quad = wid >> 1;         // column quarter 0..3
    int rb   = row_base + rg * GR;

    const ulonglong2* wr0 = (const ulonglong2*)(W + (size_t)rb * DM);
    const ulonglong2* wr1 = (const ulonglong2*)(W + (size_t)(rb + 1) * DM);

    unsigned long long acc[GR][NB];
    #pragma unroll
    for (int r = 0; r < GR; r++)
        #pragma unroll
        for (int b = 0; b < NB; b++) acc[r][b] = 0ull;

    int j0 = quad * (DM / 16) + lane;       // quad*256
    int j1 = j0 + (DM / 16);                // +256 -> 8 iterations
    #pragma unroll 1
    for (int j = j0; j < j1; j += 32) {
        // W first: streaming loads (the DRAM misses enter L1tex queue first)
        ulonglong2 w0 = __ldcs(wr0 + j);
        ulonglong2 w1 = __ldcs(wr1 + j);
        // x: one batch at a time (keeps live registers low -> 4 CTAs/SM)
        #pragma unroll
        for (int b = 0; b < NB; b++) {
            ulonglong2 xv = __ldg((const ulonglong2*)(x + (size_t)b * DM) + j);
            fma2(acc[0][b], w0.x, xv.x); fma2(acc[0][b], w0.y, xv.y);
            fma2(acc[1][b], w1.x, xv.x); fma2(acc[1][b], w1.y, xv.y);
        }
    }

    float val = 0.0f;
    #pragma unroll
    for (int r = 0; r < GR; r++) {
        #pragma unroll
        for (int b = 0; b < NB; b++) {
            float2 f = upk(acc[r][b]);
            float s = wredsum(f.x + f.y);
            if (lane == r * NB + b) val = s;
        }
    }

    __shared__ float sm[8][16];
    if (lane < 16) sm[wid][lane] = val;
    __syncthreads();

    if (threadIdx.x < 32) {
        int r = lane >> 3;           // 0..3  (row within block)
        int b = lane & 7;            // batch
        int rg2 = r >> 1;            // which row-group
        int ri  = r & 1;             // row within group
        float v = sm[0 * 2 + rg2][ri * NB + b]
                + sm[1 * 2 + rg2][ri * NB + b]
                + sm[2 * 2 + rg2][ri * NB + b]
                + sm[3 * 2 + rg2][ri * NB + b];
        int row = row_base + r;
        y[(size_t)b * DM + row] = (v + bias[row]) * scale;
    }
}

// Merged QKV: 3072 blocks; [0,1024) Q, [1024,2048) K, [2048,3072) V.
__global__ void __launch_bounds__(256, 4) qkv_gemv_kernel(
    const float* __restrict__ xq, const float* __restrict__ xk, const float* __restrict__ xv,
    const float* __restrict__ Wq, const float* __restrict__ bq,
    const float* __restrict__ Wk, const float* __restrict__ bk,
    const float* __restrict__ Wv, const float* __restrict__ bv)
{
    int mat = blockIdx.x >> 10;
    int rb  = (blockIdx.x & 1023) << 2;
    if (mat == 0)
        gemv_block(Wq, bq, xq, g_qkv,               0.08838834764831845f, rb);
    else if (mat == 1)
        gemv_block(Wk, bk, xk, g_qkv + 1 * NB * DM, 1.0f, rb);
    else
        gemv_block(Wv, bv, xv, g_qkv + 2 * NB * DM, 1.0f, rb);
}

__global__ void __launch_bounds__(256, 4) out_gemv_kernel(
    const float* __restrict__ Wo, const float* __restrict__ bo, float* __restrict__ out)
{
    gemv_block(Wo, bo, g_attn, out, 1.0f, blockIdx.x << 2);
}

// ---------------------------------------------------------------------------
// Kernel 2: flash-decode attention partials (proven config, unchanged).
// 2048 blocks = 256 (b,h) pairs x SPLIT. Each warp owns 64 keys with a
// private online softmax, 4 keys per iteration (8 LDG.128 up front).
// Only one warp in the grid touches key 4095 (fresh k/v from g_qkv).
// ---------------------------------------------------------------------------
__device__ __forceinline__ void online_step(
    float4 k0, float4 k1, float4 k2, float4 k3,
    float4 v0, float4 v1, float4 v2, float4 v3,
    float4 q4, float& m, float& s, float4& acc)
{
    float d0 = fmaf(k0.x, q4.x, fmaf(k0.y, q4.y, fmaf(k0.z, q4.z, k0.w * q4.w)));
    float d1 = fmaf(k1.x, q4.x, fmaf(k1.y, q4.y, fmaf(k1.z, q4.z, k1.w * q4.w)));
    float d2 = fmaf(k2.x, q4.x, fmaf(k2.y, q4.y, fmaf(k2.z, q4.z, k2.w * q4.w)));
    float d3 = fmaf(k3.x, q4.x, fmaf(k3.y, q4.y, fmaf(k3.z, q4.z, k3.w * q4.w)));
    d0 = wredsum(d0); d1 = wredsum(d1); d2 = wredsum(d2); d3 = wredsum(d3);

    float mn = fmaxf(m, fmaxf(fmaxf(d0, d1), fmaxf(d2, d3)));
    float cs = __expf(m - mn);
    float p0 = __expf(d0 - mn), p1 = __expf(d1 - mn);
    float p2 = __expf(d2 - mn), p3 = __expf(d3 - mn);
    s = fmaf(s, cs, (p0 + p1) + (p2 + p3));
    acc.x = fmaf(acc.x, cs, fmaf(p0, v0.x, fmaf(p1, v1.x, fmaf(p2, v2.x, p3 * v3.x))));
    acc.y = fmaf(acc.y, cs, fmaf(p0, v0.y, fmaf(p1, v1.y, fmaf(p2, v2.y, p3 * v3.y))));
    acc.z = fmaf(acc.z, cs, fmaf(p0, v0.z, fmaf(p1, v1.z, fmaf(p2, v2.z, p3 * v3.z))));
    acc.w = fmaf(acc.w, cs, fmaf(p0, v0.w, fmaf(p1, v1.w, fmaf(p2, v2.w, p3 * v3.w))));
    m = mn;
}

__global__ void __launch_bounds__(AWARPS * 32) attn_partial_kernel(
    const float* __restrict__ kcache, const float* __restrict__ vcache)
{
    int pair  = blockIdx.x / SPLIT;
    int split = blockIdx.x - pair * SPLIT;
    int b = pair >> 5, h = pair & 31;
    int wid = threadIdx.x >> 5, lane = threadIdx.x & 31;

    float4 q4 = ((const float4*)(g_qkv + b * DM + h * DK))[lane];

    size_t cbase = (size_t)pair * MAXLEN * DK;
    const float* kc = kcache + cbase;
    const float* vc = vcache + cbase;

    int key0 = split * KEYS_PER_BLOCK + wid * KEYS_PER_WARP;

    float m = -1e30f, s = 0.0f;
    float4 acc = make_float4(0.f, 0.f, 0.f, 0.f);

    if (key0 + KEYS_PER_WARP <= CACHE_LEN) {
        // branch-free fast path (all keys from cache)
        #pragma unroll 1
        for (int kk = 0; kk < KEYS_PER_WARP; kk += 4) {
            const float* kb = kc + (size_t)(key0 + kk) * DK;
            const float* vb = vc + (size_t)(key0 + kk) * DK;
            float4 k0 = ((const float4*)(kb + 0 * DK))[lane];
            float4 k1 = ((const float4*)(kb + 1 * DK))[lane];
            float4 k2 = ((const float4*)(kb + 2 * DK))[lane];
            float4 k3 = ((const float4*)(kb + 3 * DK))[lane];
            float4 v0 = ((const float4*)(vb + 0 * DK))[lane];
            float4 v1 = ((const float4*)(vb + 1 * DK))[lane];
            float4 v2 = ((const float4*)(vb + 2 * DK))[lane];
            float4 v3 = ((const float4*)(vb + 3 * DK))[lane];
            online_step(k0, k1, k2, k3, v0, v1, v2, v3, q4, m, s, acc);
        }
    } else {
        // tail path: the single warp whose range contains key 4095
        const float* knew = g_qkv + 1 * (NB * DM) + b * DM + h * DK;
        const float* vnew = g_qkv + 2 * (NB * DM) + b * DM + h * DK;
        #pragma unroll 1
        for (int kk = 0; kk < KEYS_PER_WARP; kk += 4) {
            int key = key0 + kk;
            float4 k0 = ((const float4*)((key + 0) == CACHE_LEN ? knew : kc + (size_t)(key + 0) * DK))[lane];
            float4 k1 = ((const float4*)((key + 1) == CACHE_LEN ? knew : kc + (size_t)(key + 1) * DK))[lane];
            float4 k2 = ((const float4*)((key + 2) == CACHE_LEN ? knew : kc + (size_t)(key + 2) * DK))[lane];
            float4 k3 = ((const float4*)((key + 3) == CACHE_LEN ? knew : kc + (size_t)(key + 3) * DK))[lane];
            float4 v0 = ((const float4*)((key + 0) == CACHE_LEN ? vnew : vc + (size_t)(key + 0) * DK))[lane];
            float4 v1 = ((const float4*)((key + 1) == CACHE_LEN ? vnew : vc + (size_t)(key + 1) * DK))[lane];
            float4 v2 = ((const float4*)((key + 2) == CACHE_LEN ? vnew : vc + (size_t)(key + 2) * DK))[lane];
            float4 v3 = ((const float4*)((key + 3) == CACHE_LEN ? vnew : vc + (size_t)(key + 3) * DK))[lane];
            online_step(k0, k1, k2, k3, v0, v1, v2, v3, q4, m, s, acc);
        }
    }

    __shared__ float sm_m[AWARPS], sm_s[AWARPS];
    __shared__ float4 sm_acc[AWARPS * 32];
    if (lane == 0) { sm_m[wid] = m; sm_s[wid] = s; }
    sm_acc[wid * 32 + lane] = acc;
    __syncthreads();

    if (wid == 0) {
        float M = sm_m[0];
        #pragma unroll
        for (int w = 1; w < AWARPS; w++) M = fmaxf(M, sm_m[w]);
        float S = 0.0f;
        float4 a = make_float4(0.f, 0.f, 0.f, 0.f);
        #pragma unroll
        for (int w = 0; w < AWARPS; w++) {
            float c = __expf(sm_m[w] - M);
            S = fmaf(c, sm_s[w], S);
            float4 aw = sm_acc[w * 32 + lane];
            a.x = fmaf(c, aw.x, a.x);
            a.y = fmaf(c, aw.y, a.y);
            a.z = fmaf(c, aw.z, a.z);
            a.w = fmaf(c, aw.w, a.w);
        }
        float* base = g_part + (size_t)(pair * SPLIT + split) * PART_STRIDE;
        ((float4*)(base + 4))[lane] = a;
        if (lane == 0) { base[0] = M; base[1] = S; }
    }
}

// ---------------------------------------------------------------------------
// Kernel 3: combine SPLIT partials per (b,h) pair. 32 blocks x 8 warps.
// ---------------------------------------------------------------------------
__global__ void __launch_bounds__(256) attn_combine_kernel()
{
    int pair = blockIdx.x * 8 + (threadIdx.x >> 5);
    int lane = threadIdx.x & 31;
    int b = pair >> 5, h = pair & 31;
    const float* base = g_part + (size_t)pair * SPLIT * PART_STRIDE;

    float M = -1e30f;
    #pragma unroll
    for (int sp = 0; sp < SPLIT; sp++) M = fmaxf(M, base[sp * PART_STRIDE]);

    float S = 0.0f;
    float4 a = make_float4(0.f, 0.f, 0.f, 0.f);
    #pragma unroll
    for (int sp = 0; sp < SPLIT; sp++) {
        const float* p = base + sp * PART_STRIDE;
        float c = __expf(p[0] - M);
        S = fmaf(c, p[1], S);
        float4 aw = ((const float4*)(p + 4))[lane];
        a.x = fmaf(c, aw.x, a.x);
        a.y = fmaf(c, aw.y, a.y);
        a.z = fmaf(c, aw.z, a.z);
        a.w = fmaf(c, aw.w, a.w);
    }
    float inv = 1.0f / S;
    a.x *= inv; a.y *= inv; a.z *= inv; a.w *= inv;
    ((float4*)(g_attn + b * DM + h * DK))[lane] = a;
}

// ---------------------------------------------------------------------------
// Launch: 4 sequential kernels (graph-capturable).
// Input order: query, key, value, key_cache, value_cache,
//              Wq, bq, Wk, bk, Wv, bv, Wo, bo, cache_len
// ---------------------------------------------------------------------------
extern "C" void kernel_launch(void* const* d_in, const int* in_sizes, int n_in,
                              void* d_out, int out_size)
{
    const float* query       = (const float*)d_in[0];
    const float* key         = (const float*)d_in[1];
    const float* value       = (const float*)d_in[2];
    const float* key_cache   = (const float*)d_in[3];
    const float* value_cache = (const float*)d_in[4];
    const float* Wq = (const float*)d_in[5];
    const float* bq = (const float*)d_in[6];
    const float* Wk = (const float*)d_in[7];
    const float* bk = (const float*)d_in[8];
    const float* Wv = (const float*)d_in[9];
    const float* bv = (const float*)d_in[10];
    const float* Wo = (const float*)d_in[11];
    const float* bo = (const float*)d_in[12];
    float* out = (float*)d_out;

    qkv_gemv_kernel<<<3 * (DM / ROWS_PER_BLOCK), 256>>>(query, key, value,
                                                        Wq, bq, Wk, bk, Wv, bv);
    attn_partial_kernel<<<NPAIR * SPLIT, AWARPS * 32>>>(key_cache, value_cache);
    attn_combine_kernel<<<NPAIR / 8, 256>>>();
    out_gemv_kernel<<<DM / ROWS_PER_BLOCK, 256>>>(Wo, bo, out);
}

// round 8
// speedup vs baseline: 1.1266x; 1.1266x over previous
#include <cuda_runtime.h>
#include <math.h>

#define NB 8
#define NH 32
#define DK 128
#define DM 4096
#define MAXLEN 4096
#define CACHE_LEN 4095
#define SEQ_L 4096
#define NPAIR (NB*NH)                 // 256
#define SPLIT 16
#define KEYS_PER_BLOCK (SEQ_L/SPLIT)  // 256
#define AWARPS 8
#define KEYS_PER_WARP (KEYS_PER_BLOCK/AWARPS) // 32
#define PART_STRIDE 132               // m, s, pad, pad, vec[128]  (528B, 16B-aligned)
#define GR 4                          // rows per warp in GEMV
#define ROWS_PER_BLOCK 16             // 4 row-groups x 4 rows, 2-way column split

// Scratch (no allocations allowed in kernel_launch)
__device__ float g_qkv[3 * NB * DM];                    // q (pre-scaled) | k_new | v_new
__device__ float g_part[NPAIR * SPLIT * PART_STRIDE];   // split-K partials
__device__ float g_attn[NB * DM];                       // combined attention output

__device__ __forceinline__ float wredsum(float v) {
    v += __shfl_xor_sync(0xffffffffu, v, 16);
    v += __shfl_xor_sync(0xffffffffu, v, 8);
    v += __shfl_xor_sync(0xffffffffu, v, 4);
    v += __shfl_xor_sync(0xffffffffu, v, 2);
    v += __shfl_xor_sync(0xffffffffu, v, 1);
    return v;
}

// Packed f32x2 FMA: d = a*b + d elementwise on two packed floats.
__device__ __forceinline__ void fma2(unsigned long long& d,
                                     unsigned long long a,
                                     unsigned long long b) {
    asm("fma.rn.f32x2 %0, %1, %2, %0;" : "+l"(d) : "l"(a), "l"(b));
}
__device__ __forceinline__ float2 upk(unsigned long long v) {
    float2 r;
    asm("mov.b64 {%0, %1}, %2;" : "=f"(r.x), "=f"(r.y) : "l"(v));
    return r;
}

// ---------------------------------------------------------------------------
// GEMV block routine (R6-proven): block (256 thr, 8 warps) computes 16 output
// rows for all 8 batches. Warp w: row-group (w&3) [4 rows], column half (w>>2)
// [512 float4s -> 16 lane-strided iterations]. Halves combined via smem.
//   - W streamed with __ldcs, issued first each iteration
//   - x reused across 4 rows -> 2:1 x:W L1 wavefront ratio
// ---------------------------------------------------------------------------
__device__ __forceinline__ void gemv_block(
    const float* __restrict__ W, const float* __restrict__ bias,
    const float* __restrict__ x, float* __restrict__ y,
    float scale, int row_base)
{
    int wid  = threadIdx.x >> 5;
    int lane = threadIdx.x & 31;
    int rg   = wid & 3;          // row group 0..3 (4 rows each)
    int half = wid >> 2;         // column half 0..1
    int rb   = row_base + rg * GR;

    const ulonglong2* wr0 = (const ulonglong2*)(W + (size_t)(rb + 0) * DM);
    const ulonglong2* wr1 = (const ulonglong2*)(W + (size_t)(rb + 1) * DM);
    const ulonglong2* wr2 = (const ulonglong2*)(W + (size_t)(rb + 2) * DM);
    const ulonglong2* wr3 = (const ulonglong2*)(W + (size_t)(rb + 3) * DM);

    unsigned long long acc[GR][NB];
    #pragma unroll
    for (int r = 0; r < GR; r++)
        #pragma unroll
        for (int b = 0; b < NB; b++) acc[r][b] = 0ull;

    int j0 = half * (DM / 8) + lane;        // half*512
    int j1 = j0 + (DM / 8);                 // +512 -> 16 iterations
    #pragma unroll 1
    for (int j = j0; j < j1; j += 32) {
        // W first: streaming loads (these are the DRAM misses)
        ulonglong2 w0 = __ldcs(wr0 + j);
        ulonglong2 w1 = __ldcs(wr1 + j);
        ulonglong2 w2 = __ldcs(wr2 + j);
        ulonglong2 w3 = __ldcs(wr3 + j);
        // x: L1-resident hits, batches 0..3
        #pragma unroll
        for (int b = 0; b < 4; b++) {
            ulonglong2 xv = __ldg((const ulonglong2*)(x + (size_t)b * DM) + j);
            fma2(acc[0][b], w0.x, xv.x); fma2(acc[0][b], w0.y, xv.y);
            fma2(acc[1][b], w1.x, xv.x); fma2(acc[1][b], w1.y, xv.y);
            fma2(acc[2][b], w2.x, xv.x); fma2(acc[2][b], w2.y, xv.y);
            fma2(acc[3][b], w3.x, xv.x); fma2(acc[3][b], w3.y, xv.y);
        }
        // batches 4..7
        #pragma unroll
        for (int b = 4; b < NB; b++) {
            ulonglong2 xv = __ldg((const ulonglong2*)(x + (size_t)b * DM) + j);
            fma2(acc[0][b], w0.x, xv.x); fma2(acc[0][b], w0.y, xv.y);
            fma2(acc[1][b], w1.x, xv.x); fma2(acc[1][b], w1.y, xv.y);
            fma2(acc[2][b], w2.x, xv.x); fma2(acc[2][b], w2.y, xv.y);
            fma2(acc[3][b], w3.x, xv.x); fma2(acc[3][b], w3.y, xv.y);
        }
    }

    // Reduce 32 (row,batch) sums; lane (r*8+b) keeps its value.
    float val = 0.0f;
    #pragma unroll
    for (int r = 0; r < GR; r++) {
        #pragma unroll
        for (int b = 0; b < NB; b++) {
            float2 f = upk(acc[r][b]);
            float s = wredsum(f.x + f.y);
            if (lane == r * NB + b) val = s;
        }
    }

    __shared__ float sm[8][32];
    sm[wid][lane] = val;
    __syncthreads();

    if (wid < 4) {
        float v = sm[wid][lane] + sm[wid + 4][lane];
        int r = lane >> 3, b = lane & 7;
        int row = row_base + wid * GR + r;
        y[(size_t)b * DM + row] = (v + bias[row]) * scale;
    }
}

// Merged QKV: 768 blocks; [0,256) Q, [256,512) K, [512,768) V.
__global__ void __launch_bounds__(256, 2) qkv_gemv_kernel(
    const float* __restrict__ xq, const float* __restrict__ xk, const float* __restrict__ xv,
    const float* __restrict__ Wq, const float* __restrict__ bq,
    const float* __restrict__ Wk, const float* __restrict__ bk,
    const float* __restrict__ Wv, const float* __restrict__ bv)
{
    int mat = blockIdx.x >> 8;
    int rb  = (blockIdx.x & 255) << 4;
    if (mat == 0)
        gemv_block(Wq, bq, xq, g_qkv,               0.08838834764831845f, rb);
    else if (mat == 1)
        gemv_block(Wk, bk, xk, g_qkv + 1 * NB * DM, 1.0f, rb);
    else
        gemv_block(Wv, bv, xv, g_qkv + 2 * NB * DM, 1.0f, rb);
}

__global__ void __launch_bounds__(256, 2) out_gemv_kernel(
    const float* __restrict__ Wo, const float* __restrict__ bo, float* __restrict__ out)
{
    gemv_block(Wo, bo, g_attn, out, 1.0f, blockIdx.x << 4);
}

// ---------------------------------------------------------------------------
// Kernel 2: flash-decode attention partials. SPLIT=16 -> 4096 blocks =
// 256 (b,h) pairs x 16 splits; each warp owns 32 keys (8 iterations of
// 4 keys / 8 front-batched LDG.128). Only one warp in the grid touches
// key 4095 (fresh k/v from g_qkv).
// ---------------------------------------------------------------------------
__device__ __forceinline__ void online_step(
    float4 k0, float4 k1, float4 k2, float4 k3,
    float4 v0, float4 v1, float4 v2, float4 v3,
    float4 q4, float& m, float& s, float4& acc)
{
    float d0 = fmaf(k0.x, q4.x, fmaf(k0.y, q4.y, fmaf(k0.z, q4.z, k0.w * q4.w)));
    float d1 = fmaf(k1.x, q4.x, fmaf(k1.y, q4.y, fmaf(k1.z, q4.z, k1.w * q4.w)));
    float d2 = fmaf(k2.x, q4.x, fmaf(k2.y, q4.y, fmaf(k2.z, q4.z, k2.w * q4.w)));
    float d3 = fmaf(k3.x, q4.x, fmaf(k3.y, q4.y, fmaf(k3.z, q4.z, k3.w * q4.w)));
    d0 = wredsum(d0); d1 = wredsum(d1); d2 = wredsum(d2); d3 = wredsum(d3);

    float mn = fmaxf(m, fmaxf(fmaxf(d0, d1), fmaxf(d2, d3)));
    float cs = __expf(m - mn);
    float p0 = __expf(d0 - mn), p1 = __expf(d1 - mn);
    float p2 = __expf(d2 - mn), p3 = __expf(d3 - mn);
    s = fmaf(s, cs, (p0 + p1) + (p2 + p3));
    acc.x = fmaf(acc.x, cs, fmaf(p0, v0.x, fmaf(p1, v1.x, fmaf(p2, v2.x, p3 * v3.x))));
    acc.y = fmaf(acc.y, cs, fmaf(p0, v0.y, fmaf(p1, v1.y, fmaf(p2, v2.y, p3 * v3.y))));
    acc.z = fmaf(acc.z, cs, fmaf(p0, v0.z, fmaf(p1, v1.z, fmaf(p2, v2.z, p3 * v3.z))));
    acc.w = fmaf(acc.w, cs, fmaf(p0, v0.w, fmaf(p1, v1.w, fmaf(p2, v2.w, p3 * v3.w))));
    m = mn;
}

__global__ void __launch_bounds__(AWARPS * 32) attn_partial_kernel(
    const float* __restrict__ kcache, const float* __restrict__ vcache)
{
    int pair  = blockIdx.x >> 4;                 // /SPLIT
    int split = blockIdx.x & (SPLIT - 1);
    int b = pair >> 5, h = pair & 31;
    int wid = threadIdx.x >> 5, lane = threadIdx.x & 31;

    float4 q4 = ((const float4*)(g_qkv + b * DM + h * DK))[lane];

    size_t cbase = (size_t)pair * MAXLEN * DK;
    const float* kc = kcache + cbase;
    const float* vc = vcache + cbase;

    int key0 = split * KEYS_PER_BLOCK + wid * KEYS_PER_WARP;

    float m = -1e30f, s = 0.0f;
    float4 acc = make_float4(0.f, 0.f, 0.f, 0.f);

    if (key0 + KEYS_PER_WARP <= CACHE_LEN) {
        // branch-free fast path (all keys from cache)
        #pragma unroll 1
        for (int kk = 0; kk < KEYS_PER_WARP; kk += 4) {
            const float* kb = kc + (size_t)(key0 + kk) * DK;
            const float* vb = vc + (size_t)(key0 + kk) * DK;
            float4 k0 = ((const float4*)(kb + 0 * DK))[lane];
            float4 k1 = ((const float4*)(kb + 1 * DK))[lane];
            float4 k2 = ((const float4*)(kb + 2 * DK))[lane];
            float4 k3 = ((const float4*)(kb + 3 * DK))[lane];
            float4 v0 = ((const float4*)(vb + 0 * DK))[lane];
            float4 v1 = ((const float4*)(vb + 1 * DK))[lane];
            float4 v2 = ((const float4*)(vb + 2 * DK))[lane];
            float4 v3 = ((const float4*)(vb + 3 * DK))[lane];
            online_step(k0, k1, k2, k3, v0, v1, v2, v3, q4, m, s, acc);
        }
    } else {
        // tail path: the single warp whose range contains key 4095
        const float* knew = g_qkv + 1 * (NB * DM) + b * DM + h * DK;
        const float* vnew = g_qkv + 2 * (NB * DM) + b * DM + h * DK;
        #pragma unroll 1
        for (int kk = 0; kk < KEYS_PER_WARP; kk += 4) {
            int key = key0 + kk;
            float4 k0 = ((const float4*)((key + 0) == CACHE_LEN ? knew : kc + (size_t)(key + 0) * DK))[lane];
            float4 k1 = ((const float4*)((key + 1) == CACHE_LEN ? knew : kc + (size_t)(key + 1) * DK))[lane];
            float4 k2 = ((const float4*)((key + 2) == CACHE_LEN ? knew : kc + (size_t)(key + 2) * DK))[lane];
            float4 k3 = ((const float4*)((key + 3) == CACHE_LEN ? knew : kc + (size_t)(key + 3) * DK))[lane];
            float4 v0 = ((const float4*)((key + 0) == CACHE_LEN ? vnew : vc + (size_t)(key + 0) * DK))[lane];
            float4 v1 = ((const float4*)((key + 1) == CACHE_LEN ? vnew : vc + (size_t)(key + 1) * DK))[lane];
            float4 v2 = ((const float4*)((key + 2) == CACHE_LEN ? vnew : vc + (size_t)(key + 2) * DK))[lane];
            float4 v3 = ((const float4*)((key + 3) == CACHE_LEN ? vnew : vc + (size_t)(key + 3) * DK))[lane];
            online_step(k0, k1, k2, k3, v0, v1, v2, v3, q4, m, s, acc);
        }
    }

    __shared__ float sm_m[AWARPS], sm_s[AWARPS];
    __shared__ float4 sm_acc[AWARPS * 32];
    if (lane == 0) { sm_m[wid] = m; sm_s[wid] = s; }
    sm_acc[wid * 32 + lane] = acc;
    __syncthreads();

    if (wid == 0) {
        float M = sm_m[0];
        #pragma unroll
        for (int w = 1; w < AWARPS; w++) M = fmaxf(M, sm_m[w]);
        float S = 0.0f;
        float4 a = make_float4(0.f, 0.f, 0.f, 0.f);
        #pragma unroll
        for (int w = 0; w < AWARPS; w++) {
            float c = __expf(sm_m[w] - M);
            S = fmaf(c, sm_s[w], S);
            float4 aw = sm_acc[w * 32 + lane];
            a.x = fmaf(c, aw.x, a.x);
            a.y = fmaf(c, aw.y, a.y);
            a.z = fmaf(c, aw.z, a.z);
            a.w = fmaf(c, aw.w, a.w);
        }
        float* base = g_part + (size_t)(pair * SPLIT + split) * PART_STRIDE;
        ((float4*)(base + 4))[lane] = a;
        if (lane == 0) { base[0] = M; base[1] = S; }
    }
}

// ---------------------------------------------------------------------------
// Kernel 3: combine SPLIT partials per (b,h) pair. 32 blocks x 8 warps.
// ---------------------------------------------------------------------------
__global__ void __launch_bounds__(256) attn_combine_kernel()
{
    int pair = blockIdx.x * 8 + (threadIdx.x >> 5);
    int lane = threadIdx.x & 31;
    int b = pair >> 5, h = pair & 31;
    const float* base = g_part + (size_t)pair * SPLIT * PART_STRIDE;

    float M = -1e30f;
    #pragma unroll
    for (int sp = 0; sp < SPLIT; sp++) M = fmaxf(M, base[sp * PART_STRIDE]);

    float S = 0.0f;
    float4 a = make_float4(0.f, 0.f, 0.f, 0.f);
    #pragma unroll
    for (int sp = 0; sp < SPLIT; sp++) {
        const float* p = base + sp * PART_STRIDE;
        float c = __expf(p[0] - M);
        S = fmaf(c, p[1], S);
        float4 aw = ((const float4*)(p + 4))[lane];
        a.x = fmaf(c, aw.x, a.x);
        a.y = fmaf(c, aw.y, a.y);
        a.z = fmaf(c, aw.z, a.z);
        a.w = fmaf(c, aw.w, a.w);
    }
    float inv = 1.0f / S;
    a.x *= inv; a.y *= inv; a.z *= inv; a.w *= inv;
    ((float4*)(g_attn + b * DM + h * DK))[lane] = a;
}

// ---------------------------------------------------------------------------
// Launch: 4 sequential kernels (graph-capturable).
// Input order: query, key, value, key_cache, value_cache,
//              Wq, bq, Wk, bk, Wv, bv, Wo, bo, cache_len
// ---------------------------------------------------------------------------
extern "C" void kernel_launch(void* const* d_in, const int* in_sizes, int n_in,
                              void* d_out, int out_size)
{
    const float* query       = (const float*)d_in[0];
    const float* key         = (const float*)d_in[1];
    const float* value       = (const float*)d_in[2];
    const float* key_cache   = (const float*)d_in[3];
    const float* value_cache = (const float*)d_in[4];
    const float* Wq = (const float*)d_in[5];
    const float* bq = (const float*)d_in[6];
    const float* Wk = (const float*)d_in[7];
    const float* bk = (const float*)d_in[8];
    const float* Wv = (const float*)d_in[9];
    const float* bv = (const float*)d_in[10];
    const float* Wo = (const float*)d_in[11];
    const float* bo = (const float*)d_in[12];
    float* out = (float*)d_out;

    qkv_gemv_kernel<<<3 * (DM / ROWS_PER_BLOCK), 256>>>(query, key, value,
                                                        Wq, bq, Wk, bk, Wv, bv);
    attn_partial_kernel<<<NPAIR * SPLIT, AWARPS * 32>>>(key_cache, value_cache);
    attn_combine_kernel<<<NPAIR / 8, 256>>>();
    out_gemv_kernel<<<DM / ROWS_PER_BLOCK, 256>>>(Wo, bo, out);
}